// round 6
// baseline (speedup 1.0000x reference)
#include <cuda_runtime.h>

#define B 4
#define C 32
#define H 256
#define W 256
#define H3 768
#define W3 768
#define PLANE_IN  65536
#define PLANE_OUT 589824
#define SMROW 272              // skewed row: skew(260)=268 -> pad 272
#define STRIP 16               // input row-groups per block
#define SROWS (STRIP + 2)      // 18 staged input rows
#define HALF  (STRIP / 2)      // consecutive groups per thread-half
#define NTHR 384

__device__ __forceinline__ int skew(int i) { return i + (i >> 5); }

// out[p, I, J] = x[p, reflect(I/3+I%3-1), reflect(J/3+J%3-1)]
//                * (I==767?2:1) * (J==767?2:1)
__global__ __launch_bounds__(NTHR)
void deform_roll_kernel(const float* __restrict__ x, float* __restrict__ out) {
    __shared__ float sm[SROWS][SMROW];

    const int tid   = threadIdx.x;
    const int base  = blockIdx.x * STRIP;
    const int plane = blockIdx.y;

    const float* __restrict__ xp = x + (size_t)plane * PLANE_IN;

    // ---- stage SROWS reflected input rows: 18*64 = 1152 = 3*384 float4 ----
#pragma unroll
    for (int k = 0; k < 3; ++k) {
        const int idx = tid + NTHR * k;
        const int s  = idx >> 6;
        const int c4 = idx & 63;
        int ri = base - 1 + s;
        ri = (ri < 0) ? 1 : ((ri > H - 1) ? H - 2 : ri);
        const float4 v = __ldcs(reinterpret_cast<const float4*>(xp + ri * W) + c4);
        float* r = sm[s];
        const int b0 = 4 * c4 + 4;
        r[skew(b0)]     = v.x;
        r[skew(b0 + 1)] = v.y;
        r[skew(b0 + 2)] = v.z;
        r[skew(b0 + 3)] = v.w;
        if (c4 == 0)  r[3]   = v.y;     // col -1  -> x[1]
        if (c4 == 63) r[268] = v.z;     // col 256 -> x[254]
    }
    __syncthreads();

    // ---- compute: half h walks consecutive groups; t = float4 col in row ----
    const int h = (tid >= 192) ? 1 : 0;
    const int t = tid - 192 * h;        // 0..191
    const int m = t % 3;
    const int q = t / 3;

    // distinct column idx offsets per m:  m=0:{3,4,5} m=1:{5,6,6} m=2:{7,6,8}
    const int s0 = skew(4 * q + 3 + 2 * m);
    const int s1 = skew(4 * q + (m ? 6 : 4));
    const int s2 = skew(4 * q + 5 + m + (m >> 1));
    const bool m0 = (m == 0);
    const bool m2 = (m == 2);
    const float wmul = (t == 191) ? 2.0f : 1.0f;   // J=767 col weight

    const int g0 = h * HALF;            // local first group (0 or 8)
    float* __restrict__ opl = out + (size_t)plane * PLANE_OUT;

    // load one smem row's 4 store-ready values
    auto loadrow = [&](int sr, float4& v) {
        const float* r = sm[sr];
        const float L0 = r[s0];
        const float L1 = r[s1];
        const float L2 = r[s2];
        v.x = L0;
        v.y = L1;
        v.z = m0 ? L2 : L0;
        v.w = (m2 ? L2 : L1) * wmul;
    };

    float4 a, b, c;
    loadrow(g0,     a);
    loadrow(g0 + 1, b);

#pragma unroll
    for (int gg = 0; gg < HALF; ++gg) {
        const int gl = g0 + gg;
        const int ig = base + gl;
        loadrow(gl + 2, c);

        float4 c2v = c;
        if (ig == H - 1) {              // output row I=767: weight 2
            c2v.x *= 2.0f; c2v.y *= 2.0f; c2v.z *= 2.0f; c2v.w *= 2.0f;
        }
        // wmul already applied to .w; fix .x/.y/.z double-scale? no: wmul only on .w of every row — correct per derivation.

        float4* __restrict__ op =
            reinterpret_cast<float4*>(opl + (size_t)(3 * ig) * W3) + t;
        __stcs(op,                 a);
        __stcs(op +     (W3 / 4),  b);
        __stcs(op + 2 * (W3 / 4),  c2v);

        a = b;
        b = c;
    }
}

extern "C" void kernel_launch(void* const* d_in, const int* in_sizes, int n_in,
                              void* d_out, int out_size) {
    const float* x = (const float*)d_in[0];
    float* out = (float*)d_out;
    (void)in_sizes; (void)n_in; (void)out_size;

    dim3 grid(H / STRIP, B * C);   // 16 x 128 = 2048 blocks
    deform_roll_kernel<<<grid, NTHR>>>(x, out);
}

// round 7
// speedup vs baseline: 1.0032x; 1.0032x over previous
#include <cuda_runtime.h>

#define B 4
#define C 32
#define H 256
#define W 256
#define H3 768
#define W3 768
#define PLANE_IN  65536
#define PLANE_OUT 589824
#define SMROW 272              // skewed row: skew(260)=268 -> pad 272
#define STRIP 8                // input row-groups per block
#define SROWS (STRIP + 2)      // 10 staged input rows
#define NTHR 192

__device__ __forceinline__ int skew(int i) { return i + (i >> 5); }

// out[p, I, J] = x[p, reflect(I/3+I%3-1), reflect(J/3+J%3-1)]
//                * (I==767?2:1) * (J==767?2:1)
__global__ __launch_bounds__(NTHR)
void deform_roll8_kernel(const float* __restrict__ x, float* __restrict__ out) {
    __shared__ float sm[SROWS][SMROW];

    const int tid   = threadIdx.x;       // 0..191
    const int base  = blockIdx.x * STRIP;
    const int plane = blockIdx.y;

    const float* __restrict__ xp = x + (size_t)plane * PLANE_IN;

    // ---- stage SROWS reflected rows: 10*64 = 640 float4, 192 threads ----
#pragma unroll
    for (int k = 0; k < 4; ++k) {
        const int idx = tid + NTHR * k;  // 0..767
        if (idx < SROWS * 64) {
            const int s  = idx >> 6;
            const int c4 = idx & 63;
            int ri = base - 1 + s;
            ri = (ri < 0) ? 1 : ((ri > H - 1) ? H - 2 : ri);
            const float4 v = reinterpret_cast<const float4*>(xp + ri * W)[c4];
            float* r = sm[s];
            const int b0 = 4 * c4 + 4;
            r[skew(b0)]     = v.x;
            r[skew(b0 + 1)] = v.y;
            r[skew(b0 + 2)] = v.z;
            r[skew(b0 + 3)] = v.w;
            if (c4 == 0)  r[3]   = v.y;  // col -1  -> x[1]
            if (c4 == 63) r[268] = v.z;  // col 256 -> x[254]
        }
    }
    __syncthreads();

    // ---- compute: every thread walks all 8 consecutive groups ----
    const int m = tid % 3;
    const int q = tid / 3;

    // distinct column idx offsets per m:  m=0:{3,4,5} m=1:{5,6,6} m=2:{7,6,8}
    const int s0 = skew(4 * q + 3 + 2 * m);
    const int s1 = skew(4 * q + (m ? 6 : 4));
    const int s2 = skew(4 * q + 5 + m + (m >> 1));
    const bool m0 = (m == 0);
    const bool m2 = (m == 2);
    const float wmul = (tid == 191) ? 2.0f : 1.0f;   // J=767 col weight (.w)

    float* __restrict__ opl = out + (size_t)plane * PLANE_OUT;

    auto loadrow = [&](int sr, float4& v) {
        const float* r = sm[sr];
        const float L0 = r[s0];
        const float L1 = r[s1];
        const float L2 = r[s2];
        v.x = L0;
        v.y = L1;
        v.z = m0 ? L2 : L0;
        v.w = (m2 ? L2 : L1) * wmul;
    };

    float4 a, b, c;
    loadrow(0, a);
    loadrow(1, b);

#pragma unroll
    for (int gl = 0; gl < STRIP; ++gl) {
        const int ig = base + gl;
        loadrow(gl + 2, c);

        float4 c2v = c;
        if (ig == H - 1) {               // output row I=767: weight 2
            c2v.x *= 2.0f; c2v.y *= 2.0f; c2v.z *= 2.0f; c2v.w *= 2.0f;
        }

        float4* __restrict__ op =
            reinterpret_cast<float4*>(opl + (size_t)(3 * ig) * W3) + tid;
        op[0]            = a;
        op[W3 / 4]       = b;
        op[2 * (W3 / 4)] = c2v;

        a = b;
        b = c;
    }
}

extern "C" void kernel_launch(void* const* d_in, const int* in_sizes, int n_in,
                              void* d_out, int out_size) {
    const float* x = (const float*)d_in[0];
    float* out = (float*)d_out;
    (void)in_sizes; (void)n_in; (void)out_size;

    dim3 grid(H / STRIP, B * C);   // 32 x 128 = 4096 blocks
    deform_roll8_kernel<<<grid, NTHR>>>(x, out);
}